// round 14
// baseline (speedup 1.0000x reference)
#include <cuda_runtime.h>
#include <cuda_fp16.h>
#include <math.h>
#include <cstdint>

#define N_NODES 50000
#define N_EDGES 800000
#define N_GRAPHS 100
#define D 128
#define NEG 0.01f
#define BN_EPS 1e-5f

// ---------------- scratch (device globals: allocation-free) ----------------
__device__ __half g_hw[N_NODES * D];   // messages h@W in fp16
__device__ __half g_h1[N_NODES * D];   // layer outputs in fp16 (ping)
__device__ __half g_h2[N_NODES * D];   // (pong)
__device__ int   g_degcnt[N_NODES];
__device__ float g_dinv[N_NODES];
__device__ int   g_rowptr[N_NODES + 1];
__device__ int   g_fill[N_NODES];
__device__ uint2 g_edge[N_EDGES];      // (src, enorm) packed
__device__ float g_pool[N_GRAPHS * D];
__device__ int   g_cnt[N_GRAPHS];
__device__ float g_f1[N_GRAPHS * 92];
// W^T in fp16, PRE-SWIZZLED into the ldmatrix tile layout, per layer (32KB each)
__device__ __half g_Wsw[3 * D * D];
#define SCAN_B 512
#define SCAN_G ((N_NODES + SCAN_B - 1) / SCAN_B)   // 98
__device__ int g_bsum[SCAN_G];

__device__ __forceinline__ float lrelu(float v) { return v > 0.f ? v : NEG * v; }

__device__ __forceinline__ uint32_t smem_to_u32(const void* p) {
    uint32_t a;
    asm("{ .reg .u64 t; cvta.to.shared.u64 t, %1; cvt.u32.u64 %0, t; }" : "=r"(a) : "l"(p));
    return a;
}

// tile layout: rows x 128 cols fp16, 256B/row, XOR-16B swizzle
__device__ __forceinline__ uint32_t swz(int row, int col) {
    return (uint32_t)(row * 256 + ((col * 2) ^ ((row & 7) << 4)));
}

// ---------------- prep: zero + W^T fp16 pre-swizzle ----------------
#define ZERO_BLOCKS 196
__global__ void prep_kernel(const float* __restrict__ W1, const float* __restrict__ W2,
                            const float* __restrict__ W3) {
    int b = blockIdx.x;
    if (b < ZERO_BLOCKS) {
        int i = b * 256 + threadIdx.x;
        if (i < N_NODES) g_degcnt[i] = 0;
        if (i < N_GRAPHS * D) g_pool[i] = 0.f;
        if (i < N_GRAPHS) g_cnt[i] = 0;
    } else {
        int layer = b - ZERO_BLOCKS;
        const float* W = layer == 0 ? W1 : (layer == 1 ? W2 : W3);
        char* dstb = (char*)(g_Wsw + layer * D * D);
        for (int i = threadIdx.x; i < D * D; i += 256) {
            int n = i >> 7, k = i & 127;             // tile row = n, tile col = k
            __half v = __float2half(W[k * D + n]);
            *(__half*)(dstb + swz(n, k)) = v;
        }
    }
}

// ---------------- degree over dst ----------------
__global__ void degree_kernel(const int* __restrict__ dst) {
    int e = blockIdx.x * blockDim.x + threadIdx.x;
    if (e < N_EDGES) atomicAdd(&g_degcnt[dst[e]], 1);
}

// ---------------- scan phase 1: block sums ----------------
__global__ void scan_sums_kernel() {
    __shared__ int wsum[SCAN_B / 32];
    int i = blockIdx.x * SCAN_B + threadIdx.x;
    int v = (i < N_NODES) ? g_degcnt[i] : 0;
    int lane = threadIdx.x & 31, wid = threadIdx.x >> 5;
#pragma unroll
    for (int o = 16; o > 0; o >>= 1) v += __shfl_down_sync(0xFFFFFFFFu, v, o);
    if (lane == 0) wsum[wid] = v;
    __syncthreads();
    if (threadIdx.x == 0) {
        int s = 0;
#pragma unroll
        for (int w = 0; w < SCAN_B / 32; w++) s += wsum[w];
        g_bsum[blockIdx.x] = s;
    }
}

// ---------------- scan phase 2: apply ----------------
__global__ void scan_apply_kernel() {
    __shared__ int wsum[SCAN_B / 32];
    __shared__ int blkoff;
    int t = threadIdx.x;
    if (t < 32) {
        int s = 0;
        for (int j = t; j < (int)blockIdx.x; j += 32) s += g_bsum[j];
#pragma unroll
        for (int o = 16; o > 0; o >>= 1) s += __shfl_down_sync(0xFFFFFFFFu, s, o);
        if (t == 0) blkoff = s;
    }
    int i = blockIdx.x * SCAN_B + t;
    int v = (i < N_NODES) ? g_degcnt[i] : 0;
    int lane = t & 31, wid = t >> 5;
    int val = v;
#pragma unroll
    for (int o = 1; o < 32; o <<= 1) {
        int u = __shfl_up_sync(0xFFFFFFFFu, val, o);
        if (lane >= o) val += u;
    }
    if (lane == 31) wsum[wid] = val;
    __syncthreads();
    if (t == 0) {
        int run = 0;
#pragma unroll
        for (int w = 0; w < SCAN_B / 32; w++) { int x = wsum[w]; wsum[w] = run; run += x; }
    }
    __syncthreads();
    int incl = val + wsum[wid] + blkoff;
    if (i < N_NODES) {
        g_rowptr[i + 1] = incl;
        g_fill[i] = incl - v;
        g_dinv[i] = rsqrtf((float)v + 1.0f);
    }
    if (i == 0) g_rowptr[0] = 0;
}

// ---------------- bucket edges by dst (packed uint2) ----------------
__global__ void fill_kernel(const int* __restrict__ src, const int* __restrict__ dst) {
    int e = blockIdx.x * blockDim.x + threadIdx.x;
    if (e < N_EDGES) {
        int s = src[e], d = dst[e];
        int pos = atomicAdd(&g_fill[d], 1);
        g_edge[pos] = make_uint2((uint32_t)s, __float_as_uint(g_dinv[s] * g_dinv[d]));
    }
}

// ============== HMMA GEMM: hw[N,128] = A[N,128] @ W, fp16, 128-row tiles ==============
// 512 threads / 16 warps; warp owns 16 rows x 64 cols -> acc[8][4] = 32 regs.
// smem: A 32KB + B 32KB = 64KB -> 2 CTAs/SM. A staged FIRST (cold DRAM latency
// overlapped by the L2-hot B copy that follows).
#define SM_A 0
#define SM_B 32768
#define GEMM_SMEM 65536
#define GEMM_ROWS 128

__device__ __forceinline__ void ldsm_x4(uint32_t a[4], uint32_t addr) {
    asm volatile("ldmatrix.sync.aligned.m8n8.x4.shared.b16 {%0,%1,%2,%3}, [%4];"
        : "=r"(a[0]), "=r"(a[1]), "=r"(a[2]), "=r"(a[3]) : "r"(addr));
}

__device__ __forceinline__ void mma_f16(float c[4], const uint32_t a[4], uint32_t b0, uint32_t b1) {
    asm volatile("mma.sync.aligned.m16n8k16.row.col.f32.f16.f16.f32 "
        "{%0,%1,%2,%3}, {%4,%5,%6,%7}, {%8,%9}, {%0,%1,%2,%3};"
        : "+f"(c[0]), "+f"(c[1]), "+f"(c[2]), "+f"(c[3])
        : "r"(a[0]), "r"(a[1]), "r"(a[2]), "r"(a[3]), "r"(b0), "r"(b1));
}

// stage one 128-row A tile into swizzled smem (fp32 or fp16 source)
__device__ __forceinline__ void stage_a_f32(char* smem, const float* A, int rb, int nrows, int tid) {
#pragma unroll
    for (int it = 0; it < 16; it++) {
        int i = tid + it * 512;
        int row = i >> 6, cp = i & 63;
        float2 v = make_float2(0.f, 0.f);
        if (rb + row < nrows) v = ((const float2*)A)[(size_t)(rb + row) * 64 + cp];
        *(__half2*)(smem + SM_A + swz(row, cp * 2)) = __floats2half2_rn(v.x, v.y);
    }
}
__device__ __forceinline__ void stage_a_f16(char* smem, const __half* A, int rb, int nrows, int tid) {
#pragma unroll
    for (int it = 0; it < 4; it++) {
        int i = tid + it * 512;                 // 0..2047
        int row = i >> 4, ch = i & 15;          // ch = 16B chunk (8 halves)
        uint4 v = make_uint4(0, 0, 0, 0);
        if (rb + row < nrows) v = ((const uint4*)A)[(size_t)(rb + row) * 16 + ch];
        *(uint4*)(smem + SM_A + swz(row, ch * 8)) = v;
    }
}

template <typename T>
__global__ __launch_bounds__(512, 2)
void mma_gemm_kernel(const T* __restrict__ A,
                     const __half* __restrict__ Wsw,   // pre-swizzled 32KB tile
                     __half* __restrict__ C, int nrows) {
    extern __shared__ char smem[];
    uint32_t sb = smem_to_u32(smem);
    int tid = threadIdx.x;
    int wid = tid >> 5, lane = tid & 31;
    int rb = blockIdx.x * GEMM_ROWS;

    // stage A FIRST (long-latency source)
    if (sizeof(T) == 4) stage_a_f32(smem, (const float*)A, rb, nrows, tid);
    else                stage_a_f16(smem, (const __half*)A, rb, nrows, tid);
    // stage B (L2-hot 32KB, shared by all CTAs)
    {
        const uint4* s = (const uint4*)Wsw;
        uint4* d = (uint4*)(smem + SM_B);
#pragma unroll
        for (int it = 0; it < 4; it++) d[tid + it * 512] = s[tid + it * 512];
    }
    __syncthreads();

    float acc[8][4];
#pragma unroll
    for (int n = 0; n < 8; n++)
#pragma unroll
        for (int j = 0; j < 4; j++) acc[n][j] = 0.f;

    int rowband = wid >> 1;          // 0..7 -> rows rowband*16..+15
    int colhalf = wid & 1;           // 0..1 -> cols colhalf*64..+63
    int mat = lane >> 3, r8 = lane & 7;
    int arow = rowband * 16 + r8 + (mat & 1) * 8;
    int acoloff = (mat >> 1) * 8;
    int bnbase = (mat >> 1) * 8 + r8;
    int bkoff = (mat & 1) * 8;
    uint32_t bBase = sb + SM_B + (uint32_t)(colhalf * 64 * 256);
    uint32_t aBase = sb + SM_A;

#pragma unroll
    for (int k8 = 0; k8 < 8; k8++) {
        int k0 = k8 * 16;
        uint32_t a[4];
        ldsm_x4(a, aBase + swz(arow, k0 + acoloff));
#pragma unroll
        for (int ntp = 0; ntp < 4; ntp++) {
            uint32_t b[4];
            ldsm_x4(b, bBase + (uint32_t)(ntp * 4096) + swz(bnbase, k0 + bkoff));
            mma_f16(acc[2 * ntp], a, b[0], b[1]);
            mma_f16(acc[2 * ntp + 1], a, b[2], b[3]);
        }
    }

    // epilogue: fp32 fragments -> fp16 C
    int mrow = rb + rowband * 16 + (lane >> 2);
    int nc0 = colhalf * 64 + (lane & 3) * 2;
    bool ok0 = mrow < nrows, ok1 = (mrow + 8) < nrows;
#pragma unroll
    for (int nt = 0; nt < 8; nt++) {
        if (ok0) *(__half2*)(C + (size_t)mrow * 128 + nt * 8 + nc0) =
            __floats2half2_rn(acc[nt][0], acc[nt][1]);
        if (ok1) *(__half2*)(C + (size_t)(mrow + 8) * 128 + nt * 8 + nc0) =
            __floats2half2_rn(acc[nt][2], acc[nt][3]);
    }
}

// ---------------- aggregation: fp16 gather, fp32 accum, software-pipelined ----------------
__global__ void agg_kernel(const __half* __restrict__ hw, const float* __restrict__ bias,
                           __half* __restrict__ out) {
    int warp = (blockIdx.x * blockDim.x + threadIdx.x) >> 5;
    if (warp >= N_NODES) return;
    int lane = threadIdx.x & 31;

    int beg = g_rowptr[warp];
    int end = g_rowptr[warp + 1];
    float dv = g_dinv[warp];
    float sn = dv * dv;

    const uint2* hv = (const uint2*)hw;   // lane covers cols lane*4..+3
    float4 acc;
    {
        uint2 r = hv[(size_t)warp * 32 + lane];
        float2 f0 = __half22float2(*(__half2*)&r.x);
        float2 f1 = __half22float2(*(__half2*)&r.y);
        acc = make_float4(f0.x * sn, f0.y * sn, f1.x * sn, f1.y * sn);
    }

    int e = beg;
    uint2 ed[8];
    bool have = (e + 8 <= end);
    if (have) {
#pragma unroll
        for (int j = 0; j < 8; j++) ed[j] = g_edge[e + j];
    }
    while (have) {
        // issue gathers for current batch
        uint2 r[8];
#pragma unroll
        for (int j = 0; j < 8; j++) r[j] = hv[(size_t)ed[j].x * 32 + lane];
        // prefetch next descriptor batch (overlaps gather latency)
        bool haveN = (e + 16 <= end);
        uint2 edn[8];
        if (haveN) {
#pragma unroll
            for (int j = 0; j < 8; j++) edn[j] = g_edge[e + 8 + j];
        }
        // consume current batch
#pragma unroll
        for (int j = 0; j < 8; j++) {
            float w = __uint_as_float(ed[j].y);
            float2 a0 = __half22float2(*(__half2*)&r[j].x);
            float2 b0 = __half22float2(*(__half2*)&r[j].y);
            acc.x += w * a0.x;
            acc.y += w * a0.y;
            acc.z += w * b0.x;
            acc.w += w * b0.y;
        }
#pragma unroll
        for (int j = 0; j < 8; j++) ed[j] = edn[j];
        e += 8;
        have = haveN;
    }
    if (e < end) {
        // masked chunk of 8: dummy edges use own row (L1-resident) with weight 0
        uint2 edt[8];
        uint2 r[8];
        uint32_t srcs[8];
        float ws[8];
#pragma unroll
        for (int j = 0; j < 8; j++) {
            bool ok = (e + j) < end;
            int idx = ok ? (e + j) : (end - 1);
            edt[j] = g_edge[idx];
            srcs[j] = ok ? edt[j].x : (uint32_t)warp;
            ws[j] = ok ? __uint_as_float(edt[j].y) : 0.f;
        }
#pragma unroll
        for (int j = 0; j < 8; j++) r[j] = hv[(size_t)srcs[j] * 32 + lane];
#pragma unroll
        for (int j = 0; j < 8; j++) {
            float2 a0 = __half22float2(*(__half2*)&r[j].x);
            float2 b0 = __half22float2(*(__half2*)&r[j].y);
            acc.x += ws[j] * a0.x;
            acc.y += ws[j] * a0.y;
            acc.z += ws[j] * b0.x;
            acc.w += ws[j] * b0.y;
        }
    }
    float4 b = *(const float4*)(bias + lane * 4);
    __half2 o0 = __floats2half2_rn(lrelu(acc.x + b.x), lrelu(acc.y + b.y));
    __half2 o1 = __floats2half2_rn(lrelu(acc.z + b.z), lrelu(acc.w + b.w));
    uint2 pk;
    pk.x = *(uint32_t*)&o0;
    pk.y = *(uint32_t*)&o1;
    *((uint2*)(out + (size_t)warp * 128 + lane * 4)) = pk;
}

// ---------------- per-graph sum pool + counts (fp16 input) ----------------
#define POOL_NODES 50
__global__ void pool_kernel(const __half* __restrict__ h, const int* __restrict__ batch) {
    int c = threadIdx.x;
    int base = blockIdx.x * POOL_NODES;
    int cur = batch[base];
    float acc = 0.f;
    int cnt = 0;
    for (int i = 0; i < POOL_NODES; i++) {
        int n = base + i;
        int g = batch[n];
        if (g != cur) {
            atomicAdd(&g_pool[cur * D + c], acc);
            if (c == 0) atomicAdd(&g_cnt[cur], cnt);
            acc = 0.f; cnt = 0;
            cur = g;
        }
        acc += __half2float(h[(size_t)n * D + c]);
        cnt++;
    }
    atomicAdd(&g_pool[cur * D + c], acc);
    if (c == 0) atomicAdd(&g_cnt[cur], cnt);
}

// ---------------- head1: per-graph pooled mean + ogt MLP + f1 ----------------
__global__ void head1_kernel(const float* __restrict__ ogt,
                             const float* __restrict__ Wo1, const float* __restrict__ bo1,
                             const float* __restrict__ Wo2, const float* __restrict__ bo2,
                             const float* __restrict__ Wf1, const float* __restrict__ bf1) {
    __shared__ float sf[138];
    __shared__ float o1s[20];
    int g = blockIdx.x;
    int t = threadIdx.x;

    if (t < 128) sf[t] = g_pool[g * D + t] / (float)g_cnt[g];
    if (t < 20) o1s[t] = lrelu(ogt[g] * Wo1[t] + bo1[t]);
    __syncthreads();
    if (t < 10) {
        float s = bo2[t];
#pragma unroll
        for (int k = 0; k < 20; k++) s += o1s[k] * Wo2[k * 10 + t];
        sf[128 + t] = lrelu(s);
    }
    __syncthreads();
    if (t < 92) {
        float s = bf1[t];
        for (int k = 0; k < 138; k++) s += sf[k] * Wf1[k * 92 + t];
        g_f1[g * 92 + t] = lrelu(s);
    }
}

// ---------------- head2: BN1 -> f2 -> BN2 -> out ----------------
#define H2_F1 (N_GRAPHS * 92)
#define H2_F2 (N_GRAPHS * 46)
#define HEAD2_SMEM_BYTES ((H2_F1 + H2_F2 + 92 + 92 + 46 + 46) * 4)
__global__ void head2_kernel(const float* __restrict__ g1, const float* __restrict__ be1,
                             const float* __restrict__ Wf2, const float* __restrict__ bf2,
                             const float* __restrict__ g2, const float* __restrict__ be2,
                             const float* __restrict__ Wf3, const float* __restrict__ bf3,
                             float* __restrict__ out) {
    extern __shared__ float sh[];
    float* f1 = sh;
    float* f2 = f1 + H2_F1;
    float* sc1 = f2 + H2_F2;
    float* ss1 = sc1 + 92;
    float* sc2 = ss1 + 92;
    float* ss2 = sc2 + 46;
    int t = threadIdx.x;
    const int NT = 512;

    for (int i = t; i < H2_F1; i += NT) f1[i] = g_f1[i];
    __syncthreads();

    if (t < 92) {
        float m = 0.f;
        for (int g = 0; g < N_GRAPHS; g++) m += f1[g * 92 + t];
        m *= (1.0f / N_GRAPHS);
        float var = 0.f;
        for (int g = 0; g < N_GRAPHS; g++) {
            float d = f1[g * 92 + t] - m;
            var += d * d;
        }
        var *= (1.0f / N_GRAPHS);
        float rs = rsqrtf(var + BN_EPS);
        sc1[t] = g1[t] * rs;
        ss1[t] = be1[t] - m * g1[t] * rs;
    }
    __syncthreads();

    for (int idx = t; idx < N_GRAPHS * 46; idx += NT) {
        int g = idx / 46, j = idx % 46;
        float s = bf2[j];
        for (int k = 0; k < 92; k++)
            s += (f1[g * 92 + k] * sc1[k] + ss1[k]) * Wf2[k * 46 + j];
        f2[g * 46 + j] = lrelu(s);
    }
    __syncthreads();

    if (t < 46) {
        float m = 0.f;
        for (int g = 0; g < N_GRAPHS; g++) m += f2[g * 46 + t];
        m *= (1.0f / N_GRAPHS);
        float var = 0.f;
        for (int g = 0; g < N_GRAPHS; g++) {
            float d = f2[g * 46 + t] - m;
            var += d * d;
        }
        var *= (1.0f / N_GRAPHS);
        float rs = rsqrtf(var + BN_EPS);
        sc2[t] = g2[t] * rs;
        ss2[t] = be2[t] - m * g2[t] * rs;
    }
    __syncthreads();

    if (t < N_GRAPHS) {
        float s = bf3[0];
#pragma unroll
        for (int k = 0; k < 46; k++)
            s += (f2[t * 46 + k] * sc2[k] + ss2[k]) * Wf3[k];
        out[t] = s;
    }
}

// ---------------- launch ----------------
extern "C" void kernel_launch(void* const* d_in, const int* in_sizes, int n_in,
                              void* d_out, int out_size) {
    const float* x    = (const float*)d_in[0];
    const int*   ei   = (const int*)d_in[1];
    const int*   batch= (const int*)d_in[2];
    const float* ogt  = (const float*)d_in[3];
    const float* W1   = (const float*)d_in[4];
    const float* b1   = (const float*)d_in[5];
    const float* W2   = (const float*)d_in[6];
    const float* b2   = (const float*)d_in[7];
    const float* W3   = (const float*)d_in[8];
    const float* b3   = (const float*)d_in[9];
    const float* Wo1  = (const float*)d_in[10];
    const float* bo1  = (const float*)d_in[11];
    const float* Wo2  = (const float*)d_in[12];
    const float* bo2  = (const float*)d_in[13];
    const float* Wf1  = (const float*)d_in[14];
    const float* bf1  = (const float*)d_in[15];
    const float* g1   = (const float*)d_in[16];
    const float* be1  = (const float*)d_in[17];
    const float* Wf2  = (const float*)d_in[18];
    const float* bf2  = (const float*)d_in[19];
    const float* g2   = (const float*)d_in[20];
    const float* be2  = (const float*)d_in[21];
    const float* Wf3  = (const float*)d_in[22];
    const float* bf3  = (const float*)d_in[23];
    float* out = (float*)d_out;

    const int* src = ei;
    const int* dst = ei + N_EDGES;

    __half *hw, *h1, *h2, *wsw;
    cudaGetSymbolAddress((void**)&hw, g_hw);
    cudaGetSymbolAddress((void**)&h1, g_h1);
    cudaGetSymbolAddress((void**)&h2, g_h2);
    cudaGetSymbolAddress((void**)&wsw, g_Wsw);

    cudaFuncSetAttribute(mma_gemm_kernel<float>, cudaFuncAttributeMaxDynamicSharedMemorySize, GEMM_SMEM);
    cudaFuncSetAttribute(mma_gemm_kernel<__half>, cudaFuncAttributeMaxDynamicSharedMemorySize, GEMM_SMEM);
    cudaFuncSetAttribute(head2_kernel, cudaFuncAttributeMaxDynamicSharedMemorySize, HEAD2_SMEM_BYTES);

    // one-time host-side stream/event objects (no device memory involved)
    static cudaStream_t s2 = 0;
    static cudaEvent_t evA = 0, evB = 0;
    if (s2 == 0) {
        cudaStreamCreateWithFlags(&s2, cudaStreamNonBlocking);
        cudaEventCreateWithFlags(&evA, cudaEventDisableTiming);
        cudaEventCreateWithFlags(&evB, cudaEventDisableTiming);
    }

    const int GEMM_GRID = (N_NODES + GEMM_ROWS - 1) / GEMM_ROWS;   // 391
    const int AGG_GRID = N_NODES / 8;    // 256 threads = 8 warps/block

    // stream 0: prep -> (fork) -> CSR chain; s2: gemm1 in parallel
    prep_kernel<<<ZERO_BLOCKS + 3, 256>>>(W1, W2, W3);
    cudaEventRecord(evA, 0);

    degree_kernel<<<(N_EDGES + 255) / 256, 256>>>(dst);
    scan_sums_kernel<<<SCAN_G, SCAN_B>>>();

    cudaStreamWaitEvent(s2, evA, 0);
    mma_gemm_kernel<float><<<GEMM_GRID, 512, GEMM_SMEM, s2>>>(x, wsw, hw, N_NODES);
    cudaEventRecord(evB, s2);

    scan_apply_kernel<<<SCAN_G, SCAN_B>>>();
    fill_kernel<<<(N_EDGES + 255) / 256, 256>>>(src, dst);

    cudaStreamWaitEvent(0, evB, 0);   // join gemm1 before agg1

    agg_kernel<<<AGG_GRID, 256>>>(hw, b1, h1);

    mma_gemm_kernel<__half><<<GEMM_GRID, 512, GEMM_SMEM>>>(h1, wsw + D * D, hw, N_NODES);
    agg_kernel<<<AGG_GRID, 256>>>(hw, b2, h2);

    mma_gemm_kernel<__half><<<GEMM_GRID, 512, GEMM_SMEM>>>(h2, wsw + 2 * D * D, hw, N_NODES);
    agg_kernel<<<AGG_GRID, 256>>>(hw, b3, h1);

    pool_kernel<<<N_NODES / POOL_NODES, 128>>>(h1, batch);

    head1_kernel<<<N_GRAPHS, 128>>>(ogt, Wo1, bo1, Wo2, bo2, Wf1, bf1);
    head2_kernel<<<1, 512, HEAD2_SMEM_BYTES>>>(g1, be1, Wf2, bf2, g2, be2, Wf3, bf3, out);
}

// round 15
// speedup vs baseline: 1.1332x; 1.1332x over previous
#include <cuda_runtime.h>
#include <cuda_fp16.h>
#include <math.h>
#include <cstdint>

#define N_NODES 50000
#define N_EDGES 800000
#define N_GRAPHS 100
#define D 128
#define NEG 0.01f
#define BN_EPS 1e-5f

// ---------------- scratch (device globals: allocation-free) ----------------
__device__ __half g_hw[N_NODES * D];   // messages h@W in fp16
__device__ __half g_h1[N_NODES * D];   // layer outputs in fp16 (ping)
__device__ __half g_h2[N_NODES * D];   // (pong)
__device__ int   g_degcnt[N_NODES];
__device__ float g_dinv[N_NODES];
__device__ int   g_rowptr[N_NODES + 1];
__device__ int   g_fill[N_NODES];
__device__ uint2 g_edge[N_EDGES];      // (src, enorm) packed
__device__ float g_pool[N_GRAPHS * D];
__device__ int   g_cnt[N_GRAPHS];
__device__ float g_f1[N_GRAPHS * 92];
// W^T in fp16, PRE-SWIZZLED into the ldmatrix tile layout, per layer (32KB each)
__device__ __half g_Wsw[3 * D * D];
#define SCAN_B 512
#define SCAN_G ((N_NODES + SCAN_B - 1) / SCAN_B)   // 98
__device__ int g_bsum[SCAN_G];

__device__ __forceinline__ float lrelu(float v) { return v > 0.f ? v : NEG * v; }

__device__ __forceinline__ uint32_t smem_to_u32(const void* p) {
    uint32_t a;
    asm("{ .reg .u64 t; cvta.to.shared.u64 t, %1; cvt.u32.u64 %0, t; }" : "=r"(a) : "l"(p));
    return a;
}

// tile layout: rows x 128 cols fp16, 256B/row, XOR-16B swizzle
__device__ __forceinline__ uint32_t swz(int row, int col) {
    return (uint32_t)(row * 256 + ((col * 2) ^ ((row & 7) << 4)));
}

// ---------------- prep: zero + W^T fp16 pre-swizzle ----------------
#define ZERO_BLOCKS 196
__global__ void prep_kernel(const float* __restrict__ W1, const float* __restrict__ W2,
                            const float* __restrict__ W3) {
    int b = blockIdx.x;
    if (b < ZERO_BLOCKS) {
        int i = b * 256 + threadIdx.x;
        if (i < N_NODES) g_degcnt[i] = 0;
        if (i < N_GRAPHS * D) g_pool[i] = 0.f;
        if (i < N_GRAPHS) g_cnt[i] = 0;
    } else {
        int layer = b - ZERO_BLOCKS;
        const float* W = layer == 0 ? W1 : (layer == 1 ? W2 : W3);
        char* dstb = (char*)(g_Wsw + layer * D * D);
        for (int i = threadIdx.x; i < D * D; i += 256) {
            int n = i >> 7, k = i & 127;             // tile row = n, tile col = k
            __half v = __float2half(W[k * D + n]);
            *(__half*)(dstb + swz(n, k)) = v;
        }
    }
}

// ---------------- degree over dst ----------------
__global__ void degree_kernel(const int* __restrict__ dst) {
    int e = blockIdx.x * blockDim.x + threadIdx.x;
    if (e < N_EDGES) atomicAdd(&g_degcnt[dst[e]], 1);
}

// ---------------- scan phase 1: block sums ----------------
__global__ void scan_sums_kernel() {
    __shared__ int wsum[SCAN_B / 32];
    int i = blockIdx.x * SCAN_B + threadIdx.x;
    int v = (i < N_NODES) ? g_degcnt[i] : 0;
    int lane = threadIdx.x & 31, wid = threadIdx.x >> 5;
#pragma unroll
    for (int o = 16; o > 0; o >>= 1) v += __shfl_down_sync(0xFFFFFFFFu, v, o);
    if (lane == 0) wsum[wid] = v;
    __syncthreads();
    if (threadIdx.x == 0) {
        int s = 0;
#pragma unroll
        for (int w = 0; w < SCAN_B / 32; w++) s += wsum[w];
        g_bsum[blockIdx.x] = s;
    }
}

// ---------------- scan phase 2: apply ----------------
__global__ void scan_apply_kernel() {
    __shared__ int wsum[SCAN_B / 32];
    __shared__ int blkoff;
    int t = threadIdx.x;
    if (t < 32) {
        int s = 0;
        for (int j = t; j < (int)blockIdx.x; j += 32) s += g_bsum[j];
#pragma unroll
        for (int o = 16; o > 0; o >>= 1) s += __shfl_down_sync(0xFFFFFFFFu, s, o);
        if (t == 0) blkoff = s;
    }
    int i = blockIdx.x * SCAN_B + t;
    int v = (i < N_NODES) ? g_degcnt[i] : 0;
    int lane = t & 31, wid = t >> 5;
    int val = v;
#pragma unroll
    for (int o = 1; o < 32; o <<= 1) {
        int u = __shfl_up_sync(0xFFFFFFFFu, val, o);
        if (lane >= o) val += u;
    }
    if (lane == 31) wsum[wid] = val;
    __syncthreads();
    if (t == 0) {
        int run = 0;
#pragma unroll
        for (int w = 0; w < SCAN_B / 32; w++) { int x = wsum[w]; wsum[w] = run; run += x; }
    }
    __syncthreads();
    int incl = val + wsum[wid] + blkoff;
    if (i < N_NODES) {
        g_rowptr[i + 1] = incl;
        g_fill[i] = incl - v;
        g_dinv[i] = rsqrtf((float)v + 1.0f);
    }
    if (i == 0) g_rowptr[0] = 0;
}

// ---------------- bucket edges by dst (packed uint2) ----------------
__global__ void fill_kernel(const int* __restrict__ src, const int* __restrict__ dst) {
    int e = blockIdx.x * blockDim.x + threadIdx.x;
    if (e < N_EDGES) {
        int s = src[e], d = dst[e];
        int pos = atomicAdd(&g_fill[d], 1);
        g_edge[pos] = make_uint2((uint32_t)s, __float_as_uint(g_dinv[s] * g_dinv[d]));
    }
}

// ============== HMMA GEMM: hw[N,128] = A[N,128] @ W, fp16, 128-row tiles ==============
// 512 threads / 16 warps; warp owns 16 rows x 64 cols -> acc[8][4] = 32 regs.
// smem: A 32KB + B 32KB = 64KB -> 2 CTAs/SM. One tile per CTA, B staged first
// (measured-best R12 configuration).
#define SM_A 0
#define SM_B 32768
#define GEMM_SMEM 65536
#define GEMM_ROWS 128

__device__ __forceinline__ void ldsm_x4(uint32_t a[4], uint32_t addr) {
    asm volatile("ldmatrix.sync.aligned.m8n8.x4.shared.b16 {%0,%1,%2,%3}, [%4];"
        : "=r"(a[0]), "=r"(a[1]), "=r"(a[2]), "=r"(a[3]) : "r"(addr));
}

__device__ __forceinline__ void mma_f16(float c[4], const uint32_t a[4], uint32_t b0, uint32_t b1) {
    asm volatile("mma.sync.aligned.m16n8k16.row.col.f32.f16.f16.f32 "
        "{%0,%1,%2,%3}, {%4,%5,%6,%7}, {%8,%9}, {%0,%1,%2,%3};"
        : "+f"(c[0]), "+f"(c[1]), "+f"(c[2]), "+f"(c[3])
        : "r"(a[0]), "r"(a[1]), "r"(a[2]), "r"(a[3]), "r"(b0), "r"(b1));
}

// stage one 128-row A tile into swizzled smem (fp32 or fp16 source)
__device__ __forceinline__ void stage_a_f32(char* smem, const float* A, int rb, int nrows, int tid) {
#pragma unroll
    for (int it = 0; it < 16; it++) {
        int i = tid + it * 512;
        int row = i >> 6, cp = i & 63;
        float2 v = make_float2(0.f, 0.f);
        if (rb + row < nrows) v = ((const float2*)A)[(size_t)(rb + row) * 64 + cp];
        *(__half2*)(smem + SM_A + swz(row, cp * 2)) = __floats2half2_rn(v.x, v.y);
    }
}
__device__ __forceinline__ void stage_a_f16(char* smem, const __half* A, int rb, int nrows, int tid) {
#pragma unroll
    for (int it = 0; it < 4; it++) {
        int i = tid + it * 512;                 // 0..2047
        int row = i >> 4, ch = i & 15;          // ch = 16B chunk (8 halves)
        uint4 v = make_uint4(0, 0, 0, 0);
        if (rb + row < nrows) v = ((const uint4*)A)[(size_t)(rb + row) * 16 + ch];
        *(uint4*)(smem + SM_A + swz(row, ch * 8)) = v;
    }
}

template <typename T>
__global__ __launch_bounds__(512, 2)
void mma_gemm_kernel(const T* __restrict__ A,
                     const __half* __restrict__ Wsw,   // pre-swizzled 32KB tile
                     __half* __restrict__ C, int nrows) {
    extern __shared__ char smem[];
    uint32_t sb = smem_to_u32(smem);
    int tid = threadIdx.x;
    int wid = tid >> 5, lane = tid & 31;
    int rb = blockIdx.x * GEMM_ROWS;

    // stage B (32KB)
    {
        const uint4* s = (const uint4*)Wsw;
        uint4* d = (uint4*)(smem + SM_B);
#pragma unroll
        for (int it = 0; it < 4; it++) d[tid + it * 512] = s[tid + it * 512];
    }
    // stage A
    if (sizeof(T) == 4) stage_a_f32(smem, (const float*)A, rb, nrows, tid);
    else                stage_a_f16(smem, (const __half*)A, rb, nrows, tid);
    __syncthreads();

    float acc[8][4];
#pragma unroll
    for (int n = 0; n < 8; n++)
#pragma unroll
        for (int j = 0; j < 4; j++) acc[n][j] = 0.f;

    int rowband = wid >> 1;          // 0..7 -> rows rowband*16..+15
    int colhalf = wid & 1;           // 0..1 -> cols colhalf*64..+63
    int mat = lane >> 3, r8 = lane & 7;
    int arow = rowband * 16 + r8 + (mat & 1) * 8;
    int acoloff = (mat >> 1) * 8;
    int bnbase = (mat >> 1) * 8 + r8;
    int bkoff = (mat & 1) * 8;
    uint32_t bBase = sb + SM_B + (uint32_t)(colhalf * 64 * 256);
    uint32_t aBase = sb + SM_A;

#pragma unroll
    for (int k8 = 0; k8 < 8; k8++) {
        int k0 = k8 * 16;
        uint32_t a[4];
        ldsm_x4(a, aBase + swz(arow, k0 + acoloff));
#pragma unroll
        for (int ntp = 0; ntp < 4; ntp++) {
            uint32_t b[4];
            ldsm_x4(b, bBase + (uint32_t)(ntp * 4096) + swz(bnbase, k0 + bkoff));
            mma_f16(acc[2 * ntp], a, b[0], b[1]);
            mma_f16(acc[2 * ntp + 1], a, b[2], b[3]);
        }
    }

    // epilogue: fp32 fragments -> fp16 C
    int mrow = rb + rowband * 16 + (lane >> 2);
    int nc0 = colhalf * 64 + (lane & 3) * 2;
    bool ok0 = mrow < nrows, ok1 = (mrow + 8) < nrows;
#pragma unroll
    for (int nt = 0; nt < 8; nt++) {
        if (ok0) *(__half2*)(C + (size_t)mrow * 128 + nt * 8 + nc0) =
            __floats2half2_rn(acc[nt][0], acc[nt][1]);
        if (ok1) *(__half2*)(C + (size_t)(mrow + 8) * 128 + nt * 8 + nc0) =
            __floats2half2_rn(acc[nt][2], acc[nt][3]);
    }
}

// ---------------- aggregation: fp16 gather, fp32 accum, masked-chunk tail ----------------
// (R12 measured-best structure; only change: edge descriptors via __ldcs —
// single-use streaming data, keeps L1 for the reused hw rows)
__global__ void agg_kernel(const __half* __restrict__ hw, const float* __restrict__ bias,
                           __half* __restrict__ out) {
    int warp = (blockIdx.x * blockDim.x + threadIdx.x) >> 5;
    if (warp >= N_NODES) return;
    int lane = threadIdx.x & 31;

    int beg = g_rowptr[warp];
    int end = g_rowptr[warp + 1];
    float dv = g_dinv[warp];
    float sn = dv * dv;

    const uint2* hv = (const uint2*)hw;   // lane covers cols lane*4..+3
    float4 acc;
    {
        uint2 r = hv[(size_t)warp * 32 + lane];
        float2 f0 = __half22float2(*(__half2*)&r.x);
        float2 f1 = __half22float2(*(__half2*)&r.y);
        acc = make_float4(f0.x * sn, f0.y * sn, f1.x * sn, f1.y * sn);
    }

    int e = beg;
    for (; e + 8 <= end; e += 8) {
        uint2 ed[8];
        uint2 r[8];
#pragma unroll
        for (int j = 0; j < 8; j++) ed[j] = __ldcs(&g_edge[e + j]);
#pragma unroll
        for (int j = 0; j < 8; j++) r[j] = hv[(size_t)ed[j].x * 32 + lane];
#pragma unroll
        for (int j = 0; j < 8; j++) {
            float w = __uint_as_float(ed[j].y);
            float2 a0 = __half22float2(*(__half2*)&r[j].x);
            float2 b0 = __half22float2(*(__half2*)&r[j].y);
            acc.x += w * a0.x;
            acc.y += w * a0.y;
            acc.z += w * b0.x;
            acc.w += w * b0.y;
        }
    }
    if (e < end) {
        // masked chunk of 8: dummy edges use own row (L1-resident) with weight 0
        uint2 ed[8];
        uint2 r[8];
        uint32_t srcs[8];
        float ws[8];
#pragma unroll
        for (int j = 0; j < 8; j++) {
            bool ok = (e + j) < end;
            int idx = ok ? (e + j) : (end - 1);
            ed[j] = __ldcs(&g_edge[idx]);
            srcs[j] = ok ? ed[j].x : (uint32_t)warp;
            ws[j] = ok ? __uint_as_float(ed[j].y) : 0.f;
        }
#pragma unroll
        for (int j = 0; j < 8; j++) r[j] = hv[(size_t)srcs[j] * 32 + lane];
#pragma unroll
        for (int j = 0; j < 8; j++) {
            float2 a0 = __half22float2(*(__half2*)&r[j].x);
            float2 b0 = __half22float2(*(__half2*)&r[j].y);
            acc.x += ws[j] * a0.x;
            acc.y += ws[j] * a0.y;
            acc.z += ws[j] * b0.x;
            acc.w += ws[j] * b0.y;
        }
    }
    float4 b = *(const float4*)(bias + lane * 4);
    __half2 o0 = __floats2half2_rn(lrelu(acc.x + b.x), lrelu(acc.y + b.y));
    __half2 o1 = __floats2half2_rn(lrelu(acc.z + b.z), lrelu(acc.w + b.w));
    uint2 pk;
    pk.x = *(uint32_t*)&o0;
    pk.y = *(uint32_t*)&o1;
    *((uint2*)(out + (size_t)warp * 128 + lane * 4)) = pk;
}

// ---------------- per-graph sum pool + counts (fp16 input) ----------------
#define POOL_NODES 50
__global__ void pool_kernel(const __half* __restrict__ h, const int* __restrict__ batch) {
    int c = threadIdx.x;
    int base = blockIdx.x * POOL_NODES;
    int cur = batch[base];
    float acc = 0.f;
    int cnt = 0;
    for (int i = 0; i < POOL_NODES; i++) {
        int n = base + i;
        int g = batch[n];
        if (g != cur) {
            atomicAdd(&g_pool[cur * D + c], acc);
            if (c == 0) atomicAdd(&g_cnt[cur], cnt);
            acc = 0.f; cnt = 0;
            cur = g;
        }
        acc += __half2float(h[(size_t)n * D + c]);
        cnt++;
    }
    atomicAdd(&g_pool[cur * D + c], acc);
    if (c == 0) atomicAdd(&g_cnt[cur], cnt);
}

// ---------------- head1: per-graph pooled mean + ogt MLP + f1 ----------------
__global__ void head1_kernel(const float* __restrict__ ogt,
                             const float* __restrict__ Wo1, const float* __restrict__ bo1,
                             const float* __restrict__ Wo2, const float* __restrict__ bo2,
                             const float* __restrict__ Wf1, const float* __restrict__ bf1) {
    __shared__ float sf[138];
    __shared__ float o1s[20];
    int g = blockIdx.x;
    int t = threadIdx.x;

    if (t < 128) sf[t] = g_pool[g * D + t] / (float)g_cnt[g];
    if (t < 20) o1s[t] = lrelu(ogt[g] * Wo1[t] + bo1[t]);
    __syncthreads();
    if (t < 10) {
        float s = bo2[t];
#pragma unroll
        for (int k = 0; k < 20; k++) s += o1s[k] * Wo2[k * 10 + t];
        sf[128 + t] = lrelu(s);
    }
    __syncthreads();
    if (t < 92) {
        float s = bf1[t];
        for (int k = 0; k < 138; k++) s += sf[k] * Wf1[k * 92 + t];
        g_f1[g * 92 + t] = lrelu(s);
    }
}

// ---------------- head2: BN1 -> f2 -> BN2 -> out ----------------
#define H2_F1 (N_GRAPHS * 92)
#define H2_F2 (N_GRAPHS * 46)
#define HEAD2_SMEM_BYTES ((H2_F1 + H2_F2 + 92 + 92 + 46 + 46) * 4)
__global__ void head2_kernel(const float* __restrict__ g1, const float* __restrict__ be1,
                             const float* __restrict__ Wf2, const float* __restrict__ bf2,
                             const float* __restrict__ g2, const float* __restrict__ be2,
                             const float* __restrict__ Wf3, const float* __restrict__ bf3,
                             float* __restrict__ out) {
    extern __shared__ float sh[];
    float* f1 = sh;
    float* f2 = f1 + H2_F1;
    float* sc1 = f2 + H2_F2;
    float* ss1 = sc1 + 92;
    float* sc2 = ss1 + 92;
    float* ss2 = sc2 + 46;
    int t = threadIdx.x;
    const int NT = 512;

    for (int i = t; i < H2_F1; i += NT) f1[i] = g_f1[i];
    __syncthreads();

    if (t < 92) {
        float m = 0.f;
        for (int g = 0; g < N_GRAPHS; g++) m += f1[g * 92 + t];
        m *= (1.0f / N_GRAPHS);
        float var = 0.f;
        for (int g = 0; g < N_GRAPHS; g++) {
            float d = f1[g * 92 + t] - m;
            var += d * d;
        }
        var *= (1.0f / N_GRAPHS);
        float rs = rsqrtf(var + BN_EPS);
        sc1[t] = g1[t] * rs;
        ss1[t] = be1[t] - m * g1[t] * rs;
    }
    __syncthreads();

    for (int idx = t; idx < N_GRAPHS * 46; idx += NT) {
        int g = idx / 46, j = idx % 46;
        float s = bf2[j];
        for (int k = 0; k < 92; k++)
            s += (f1[g * 92 + k] * sc1[k] + ss1[k]) * Wf2[k * 46 + j];
        f2[g * 46 + j] = lrelu(s);
    }
    __syncthreads();

    if (t < 46) {
        float m = 0.f;
        for (int g = 0; g < N_GRAPHS; g++) m += f2[g * 46 + t];
        m *= (1.0f / N_GRAPHS);
        float var = 0.f;
        for (int g = 0; g < N_GRAPHS; g++) {
            float d = f2[g * 46 + t] - m;
            var += d * d;
        }
        var *= (1.0f / N_GRAPHS);
        float rs = rsqrtf(var + BN_EPS);
        sc2[t] = g2[t] * rs;
        ss2[t] = be2[t] - m * g2[t] * rs;
    }
    __syncthreads();

    if (t < N_GRAPHS) {
        float s = bf3[0];
#pragma unroll
        for (int k = 0; k < 46; k++)
            s += (f2[t * 46 + k] * sc2[k] + ss2[k]) * Wf3[k];
        out[t] = s;
    }
}

// ---------------- launch ----------------
extern "C" void kernel_launch(void* const* d_in, const int* in_sizes, int n_in,
                              void* d_out, int out_size) {
    const float* x    = (const float*)d_in[0];
    const int*   ei   = (const int*)d_in[1];
    const int*   batch= (const int*)d_in[2];
    const float* ogt  = (const float*)d_in[3];
    const float* W1   = (const float*)d_in[4];
    const float* b1   = (const float*)d_in[5];
    const float* W2   = (const float*)d_in[6];
    const float* b2   = (const float*)d_in[7];
    const float* W3   = (const float*)d_in[8];
    const float* b3   = (const float*)d_in[9];
    const float* Wo1  = (const float*)d_in[10];
    const float* bo1  = (const float*)d_in[11];
    const float* Wo2  = (const float*)d_in[12];
    const float* bo2  = (const float*)d_in[13];
    const float* Wf1  = (const float*)d_in[14];
    const float* bf1  = (const float*)d_in[15];
    const float* g1   = (const float*)d_in[16];
    const float* be1  = (const float*)d_in[17];
    const float* Wf2  = (const float*)d_in[18];
    const float* bf2  = (const float*)d_in[19];
    const float* g2   = (const float*)d_in[20];
    const float* be2  = (const float*)d_in[21];
    const float* Wf3  = (const float*)d_in[22];
    const float* bf3  = (const float*)d_in[23];
    float* out = (float*)d_out;

    const int* src = ei;
    const int* dst = ei + N_EDGES;

    __half *hw, *h1, *h2, *wsw;
    cudaGetSymbolAddress((void**)&hw, g_hw);
    cudaGetSymbolAddress((void**)&h1, g_h1);
    cudaGetSymbolAddress((void**)&h2, g_h2);
    cudaGetSymbolAddress((void**)&wsw, g_Wsw);

    cudaFuncSetAttribute(mma_gemm_kernel<float>, cudaFuncAttributeMaxDynamicSharedMemorySize, GEMM_SMEM);
    cudaFuncSetAttribute(mma_gemm_kernel<__half>, cudaFuncAttributeMaxDynamicSharedMemorySize, GEMM_SMEM);
    cudaFuncSetAttribute(head2_kernel, cudaFuncAttributeMaxDynamicSharedMemorySize, HEAD2_SMEM_BYTES);

    // one-time host-side stream/event objects (no device memory involved)
    static cudaStream_t s2 = 0;
    static cudaEvent_t evA = 0, evB = 0;
    if (s2 == 0) {
        cudaStreamCreateWithFlags(&s2, cudaStreamNonBlocking);
        cudaEventCreateWithFlags(&evA, cudaEventDisableTiming);
        cudaEventCreateWithFlags(&evB, cudaEventDisableTiming);
    }

    const int GEMM_GRID = (N_NODES + GEMM_ROWS - 1) / GEMM_ROWS;   // 391
    const int AGG_GRID = N_NODES / 16;   // 512 threads = 16 warps/block

    // stream 0: prep -> (fork) -> CSR chain; s2: gemm1 in parallel
    prep_kernel<<<ZERO_BLOCKS + 3, 256>>>(W1, W2, W3);
    cudaEventRecord(evA, 0);

    degree_kernel<<<(N_EDGES + 255) / 256, 256>>>(dst);
    scan_sums_kernel<<<SCAN_G, SCAN_B>>>();

    cudaStreamWaitEvent(s2, evA, 0);
    mma_gemm_kernel<float><<<GEMM_GRID, 512, GEMM_SMEM, s2>>>(x, wsw, hw, N_NODES);
    cudaEventRecord(evB, s2);

    scan_apply_kernel<<<SCAN_G, SCAN_B>>>();
    fill_kernel<<<(N_EDGES + 255) / 256, 256>>>(src, dst);

    cudaStreamWaitEvent(0, evB, 0);   // join gemm1 before agg1

    agg_kernel<<<AGG_GRID, 512>>>(hw, b1, h1);

    mma_gemm_kernel<__half><<<GEMM_GRID, 512, GEMM_SMEM>>>(h1, wsw + D * D, hw, N_NODES);
    agg_kernel<<<AGG_GRID, 512>>>(hw, b2, h2);

    mma_gemm_kernel<__half><<<GEMM_GRID, 512, GEMM_SMEM>>>(h2, wsw + 2 * D * D, hw, N_NODES);
    agg_kernel<<<AGG_GRID, 512>>>(hw, b3, h1);

    pool_kernel<<<N_NODES / POOL_NODES, 128>>>(h1, batch);

    head1_kernel<<<N_GRAPHS, 128>>>(ogt, Wo1, bo1, Wo2, bo2, Wf1, bf1);
    head2_kernel<<<1, 512, HEAD2_SMEM_BYTES>>>(g1, be1, Wf2, bf2, g2, be2, Wf3, bf3, out);
}

// round 16
// speedup vs baseline: 1.1385x; 1.0047x over previous
#include <cuda_runtime.h>
#include <cuda_fp16.h>
#include <math.h>
#include <cstdint>

#define N_NODES 50000
#define N_EDGES 800000
#define N_GRAPHS 100
#define D 128
#define NEG 0.01f
#define BN_EPS 1e-5f

// ---------------- scratch (device globals: allocation-free) ----------------
__device__ __half g_hw[N_NODES * D];   // messages h@W in fp16
__device__ __half g_h1[N_NODES * D];   // layer outputs in fp16 (ping)
__device__ __half g_h2[N_NODES * D];   // (pong)
__device__ int   g_degcnt[N_NODES];
__device__ float g_dinv[N_NODES];
__device__ int   g_rowptr[N_NODES + 1];
__device__ int   g_fill[N_NODES];
__device__ uint2 g_edge[N_EDGES];      // (src, enorm) packed
__device__ float g_pool[N_GRAPHS * D];
__device__ int   g_cnt[N_GRAPHS];
__device__ float g_f1[N_GRAPHS * 92];
// W^T in fp16, PRE-SWIZZLED into the ldmatrix tile layout, per layer (32KB each)
__device__ __half g_Wsw[3 * D * D];
#define SCAN_B 512
#define SCAN_G ((N_NODES + SCAN_B - 1) / SCAN_B)   // 98
__device__ int g_bsum[SCAN_G];

__device__ __forceinline__ float lrelu(float v) { return v > 0.f ? v : NEG * v; }

__device__ __forceinline__ uint32_t smem_to_u32(const void* p) {
    uint32_t a;
    asm("{ .reg .u64 t; cvta.to.shared.u64 t, %1; cvt.u32.u64 %0, t; }" : "=r"(a) : "l"(p));
    return a;
}

// tile layout: rows x 128 cols fp16, 256B/row, XOR-16B swizzle
__device__ __forceinline__ uint32_t swz(int row, int col) {
    return (uint32_t)(row * 256 + ((col * 2) ^ ((row & 7) << 4)));
}

// ---------------- prep: zero + W^T fp16 pre-swizzle ----------------
#define ZERO_BLOCKS 196
__global__ void prep_kernel(const float* __restrict__ W1, const float* __restrict__ W2,
                            const float* __restrict__ W3) {
    int b = blockIdx.x;
    if (b < ZERO_BLOCKS) {
        int i = b * 256 + threadIdx.x;
        if (i < N_NODES) g_degcnt[i] = 0;
        if (i < N_GRAPHS * D) g_pool[i] = 0.f;
        if (i < N_GRAPHS) g_cnt[i] = 0;
    } else {
        int layer = b - ZERO_BLOCKS;
        const float* W = layer == 0 ? W1 : (layer == 1 ? W2 : W3);
        char* dstb = (char*)(g_Wsw + layer * D * D);
        for (int i = threadIdx.x; i < D * D; i += 256) {
            int n = i >> 7, k = i & 127;             // tile row = n, tile col = k
            __half v = __float2half(W[k * D + n]);
            *(__half*)(dstb + swz(n, k)) = v;
        }
    }
}

// ---------------- degree over dst (2 edges/thread, int2) ----------------
__global__ void degree_kernel(const int* __restrict__ dst) {
    int p = blockIdx.x * blockDim.x + threadIdx.x;     // pair index
    if (p < N_EDGES / 2) {
        int2 d = ((const int2*)dst)[p];
        atomicAdd(&g_degcnt[d.x], 1);
        atomicAdd(&g_degcnt[d.y], 1);
    }
}

// ---------------- scan phase 1: block sums ----------------
__global__ void scan_sums_kernel() {
    __shared__ int wsum[SCAN_B / 32];
    int i = blockIdx.x * SCAN_B + threadIdx.x;
    int v = (i < N_NODES) ? g_degcnt[i] : 0;
    int lane = threadIdx.x & 31, wid = threadIdx.x >> 5;
#pragma unroll
    for (int o = 16; o > 0; o >>= 1) v += __shfl_down_sync(0xFFFFFFFFu, v, o);
    if (lane == 0) wsum[wid] = v;
    __syncthreads();
    if (threadIdx.x == 0) {
        int s = 0;
#pragma unroll
        for (int w = 0; w < SCAN_B / 32; w++) s += wsum[w];
        g_bsum[blockIdx.x] = s;
    }
}

// ---------------- scan phase 2: apply ----------------
__global__ void scan_apply_kernel() {
    __shared__ int wsum[SCAN_B / 32];
    __shared__ int blkoff;
    int t = threadIdx.x;
    if (t < 32) {
        int s = 0;
        for (int j = t; j < (int)blockIdx.x; j += 32) s += g_bsum[j];
#pragma unroll
        for (int o = 16; o > 0; o >>= 1) s += __shfl_down_sync(0xFFFFFFFFu, s, o);
        if (t == 0) blkoff = s;
    }
    int i = blockIdx.x * SCAN_B + t;
    int v = (i < N_NODES) ? g_degcnt[i] : 0;
    int lane = t & 31, wid = t >> 5;
    int val = v;
#pragma unroll
    for (int o = 1; o < 32; o <<= 1) {
        int u = __shfl_up_sync(0xFFFFFFFFu, val, o);
        if (lane >= o) val += u;
    }
    if (lane == 31) wsum[wid] = val;
    __syncthreads();
    if (t == 0) {
        int run = 0;
#pragma unroll
        for (int w = 0; w < SCAN_B / 32; w++) { int x = wsum[w]; wsum[w] = run; run += x; }
    }
    __syncthreads();
    int incl = val + wsum[wid] + blkoff;
    if (i < N_NODES) {
        g_rowptr[i + 1] = incl;
        g_fill[i] = incl - v;
        g_dinv[i] = rsqrtf((float)v + 1.0f);
    }
    if (i == 0) g_rowptr[0] = 0;
}

// ---------------- bucket edges by dst (2 edges/thread, int2) ----------------
__global__ void fill_kernel(const int* __restrict__ src, const int* __restrict__ dst) {
    int p = blockIdx.x * blockDim.x + threadIdx.x;     // pair index
    if (p < N_EDGES / 2) {
        int2 s = ((const int2*)src)[p];
        int2 d = ((const int2*)dst)[p];
        int pos0 = atomicAdd(&g_fill[d.x], 1);
        int pos1 = atomicAdd(&g_fill[d.y], 1);
        g_edge[pos0] = make_uint2((uint32_t)s.x, __float_as_uint(g_dinv[s.x] * g_dinv[d.x]));
        g_edge[pos1] = make_uint2((uint32_t)s.y, __float_as_uint(g_dinv[s.y] * g_dinv[d.y]));
    }
}

// ============== HMMA GEMM: hw[N,128] = A[N,128] @ W, fp16, 128-row tiles ==============
// 512 threads / 16 warps; warp owns 16 rows x 64 cols -> acc[8][4] = 32 regs.
// smem: A 32KB + B 32KB = 64KB -> 2 CTAs/SM. One tile per CTA, B staged first
// (measured-best R12 configuration).
#define SM_A 0
#define SM_B 32768
#define GEMM_SMEM 65536
#define GEMM_ROWS 128

__device__ __forceinline__ void ldsm_x4(uint32_t a[4], uint32_t addr) {
    asm volatile("ldmatrix.sync.aligned.m8n8.x4.shared.b16 {%0,%1,%2,%3}, [%4];"
        : "=r"(a[0]), "=r"(a[1]), "=r"(a[2]), "=r"(a[3]) : "r"(addr));
}

__device__ __forceinline__ void mma_f16(float c[4], const uint32_t a[4], uint32_t b0, uint32_t b1) {
    asm volatile("mma.sync.aligned.m16n8k16.row.col.f32.f16.f16.f32 "
        "{%0,%1,%2,%3}, {%4,%5,%6,%7}, {%8,%9}, {%0,%1,%2,%3};"
        : "+f"(c[0]), "+f"(c[1]), "+f"(c[2]), "+f"(c[3])
        : "r"(a[0]), "r"(a[1]), "r"(a[2]), "r"(a[3]), "r"(b0), "r"(b1));
}

// stage one 128-row A tile into swizzled smem (fp32 or fp16 source)
__device__ __forceinline__ void stage_a_f32(char* smem, const float* A, int rb, int nrows, int tid) {
#pragma unroll
    for (int it = 0; it < 16; it++) {
        int i = tid + it * 512;
        int row = i >> 6, cp = i & 63;
        float2 v = make_float2(0.f, 0.f);
        if (rb + row < nrows) v = ((const float2*)A)[(size_t)(rb + row) * 64 + cp];
        *(__half2*)(smem + SM_A + swz(row, cp * 2)) = __floats2half2_rn(v.x, v.y);
    }
}
__device__ __forceinline__ void stage_a_f16(char* smem, const __half* A, int rb, int nrows, int tid) {
#pragma unroll
    for (int it = 0; it < 4; it++) {
        int i = tid + it * 512;                 // 0..2047
        int row = i >> 4, ch = i & 15;          // ch = 16B chunk (8 halves)
        uint4 v = make_uint4(0, 0, 0, 0);
        if (rb + row < nrows) v = ((const uint4*)A)[(size_t)(rb + row) * 16 + ch];
        *(uint4*)(smem + SM_A + swz(row, ch * 8)) = v;
    }
}

template <typename T>
__global__ __launch_bounds__(512, 2)
void mma_gemm_kernel(const T* __restrict__ A,
                     const __half* __restrict__ Wsw,   // pre-swizzled 32KB tile
                     __half* __restrict__ C, int nrows) {
    extern __shared__ char smem[];
    uint32_t sb = smem_to_u32(smem);
    int tid = threadIdx.x;
    int wid = tid >> 5, lane = tid & 31;
    int rb = blockIdx.x * GEMM_ROWS;

    // stage B (32KB)
    {
        const uint4* s = (const uint4*)Wsw;
        uint4* d = (uint4*)(smem + SM_B);
#pragma unroll
        for (int it = 0; it < 4; it++) d[tid + it * 512] = s[tid + it * 512];
    }
    // stage A
    if (sizeof(T) == 4) stage_a_f32(smem, (const float*)A, rb, nrows, tid);
    else                stage_a_f16(smem, (const __half*)A, rb, nrows, tid);
    __syncthreads();

    float acc[8][4];
#pragma unroll
    for (int n = 0; n < 8; n++)
#pragma unroll
        for (int j = 0; j < 4; j++) acc[n][j] = 0.f;

    int rowband = wid >> 1;          // 0..7 -> rows rowband*16..+15
    int colhalf = wid & 1;           // 0..1 -> cols colhalf*64..+63
    int mat = lane >> 3, r8 = lane & 7;
    int arow = rowband * 16 + r8 + (mat & 1) * 8;
    int acoloff = (mat >> 1) * 8;
    int bnbase = (mat >> 1) * 8 + r8;
    int bkoff = (mat & 1) * 8;
    uint32_t bBase = sb + SM_B + (uint32_t)(colhalf * 64 * 256);
    uint32_t aBase = sb + SM_A;

#pragma unroll
    for (int k8 = 0; k8 < 8; k8++) {
        int k0 = k8 * 16;
        uint32_t a[4];
        ldsm_x4(a, aBase + swz(arow, k0 + acoloff));
#pragma unroll
        for (int ntp = 0; ntp < 4; ntp++) {
            uint32_t b[4];
            ldsm_x4(b, bBase + (uint32_t)(ntp * 4096) + swz(bnbase, k0 + bkoff));
            mma_f16(acc[2 * ntp], a, b[0], b[1]);
            mma_f16(acc[2 * ntp + 1], a, b[2], b[3]);
        }
    }

    // epilogue: fp32 fragments -> fp16 C
    int mrow = rb + rowband * 16 + (lane >> 2);
    int nc0 = colhalf * 64 + (lane & 3) * 2;
    bool ok0 = mrow < nrows, ok1 = (mrow + 8) < nrows;
#pragma unroll
    for (int nt = 0; nt < 8; nt++) {
        if (ok0) *(__half2*)(C + (size_t)mrow * 128 + nt * 8 + nc0) =
            __floats2half2_rn(acc[nt][0], acc[nt][1]);
        if (ok1) *(__half2*)(C + (size_t)(mrow + 8) * 128 + nt * 8 + nc0) =
            __floats2half2_rn(acc[nt][2], acc[nt][3]);
    }
}

// ---------------- aggregation: fp16 gather, fp32 accum, masked-chunk tail (R12) ----------------
__global__ void agg_kernel(const __half* __restrict__ hw, const float* __restrict__ bias,
                           __half* __restrict__ out) {
    int warp = (blockIdx.x * blockDim.x + threadIdx.x) >> 5;
    if (warp >= N_NODES) return;
    int lane = threadIdx.x & 31;

    int beg = g_rowptr[warp];
    int end = g_rowptr[warp + 1];
    float dv = g_dinv[warp];
    float sn = dv * dv;

    const uint2* hv = (const uint2*)hw;   // lane covers cols lane*4..+3
    float4 acc;
    {
        uint2 r = hv[(size_t)warp * 32 + lane];
        float2 f0 = __half22float2(*(__half2*)&r.x);
        float2 f1 = __half22float2(*(__half2*)&r.y);
        acc = make_float4(f0.x * sn, f0.y * sn, f1.x * sn, f1.y * sn);
    }

    int e = beg;
    for (; e + 8 <= end; e += 8) {
        uint2 ed[8];
        uint2 r[8];
#pragma unroll
        for (int j = 0; j < 8; j++) ed[j] = g_edge[e + j];
#pragma unroll
        for (int j = 0; j < 8; j++) r[j] = hv[(size_t)ed[j].x * 32 + lane];
#pragma unroll
        for (int j = 0; j < 8; j++) {
            float w = __uint_as_float(ed[j].y);
            float2 a0 = __half22float2(*(__half2*)&r[j].x);
            float2 b0 = __half22float2(*(__half2*)&r[j].y);
            acc.x += w * a0.x;
            acc.y += w * a0.y;
            acc.z += w * b0.x;
            acc.w += w * b0.y;
        }
    }
    if (e < end) {
        // masked chunk of 8: dummy edges use own row (L1-resident) with weight 0
        uint2 ed[8];
        uint2 r[8];
        uint32_t srcs[8];
        float ws[8];
#pragma unroll
        for (int j = 0; j < 8; j++) {
            bool ok = (e + j) < end;
            int idx = ok ? (e + j) : (end - 1);
            ed[j] = g_edge[idx];
            srcs[j] = ok ? ed[j].x : (uint32_t)warp;
            ws[j] = ok ? __uint_as_float(ed[j].y) : 0.f;
        }
#pragma unroll
        for (int j = 0; j < 8; j++) r[j] = hv[(size_t)srcs[j] * 32 + lane];
#pragma unroll
        for (int j = 0; j < 8; j++) {
            float2 a0 = __half22float2(*(__half2*)&r[j].x);
            float2 b0 = __half22float2(*(__half2*)&r[j].y);
            acc.x += ws[j] * a0.x;
            acc.y += ws[j] * a0.y;
            acc.z += ws[j] * b0.x;
            acc.w += ws[j] * b0.y;
        }
    }
    float4 b = *(const float4*)(bias + lane * 4);
    __half2 o0 = __floats2half2_rn(lrelu(acc.x + b.x), lrelu(acc.y + b.y));
    __half2 o1 = __floats2half2_rn(lrelu(acc.z + b.z), lrelu(acc.w + b.w));
    uint2 pk;
    pk.x = *(uint32_t*)&o0;
    pk.y = *(uint32_t*)&o1;
    *((uint2*)(out + (size_t)warp * 128 + lane * 4)) = pk;
}

// ---------------- per-graph sum pool + counts (fp16 input) ----------------
#define POOL_NODES 50
__global__ void pool_kernel(const __half* __restrict__ h, const int* __restrict__ batch) {
    int c = threadIdx.x;
    int base = blockIdx.x * POOL_NODES;
    int cur = batch[base];
    float acc = 0.f;
    int cnt = 0;
    for (int i = 0; i < POOL_NODES; i++) {
        int n = base + i;
        int g = batch[n];
        if (g != cur) {
            atomicAdd(&g_pool[cur * D + c], acc);
            if (c == 0) atomicAdd(&g_cnt[cur], cnt);
            acc = 0.f; cnt = 0;
            cur = g;
        }
        acc += __half2float(h[(size_t)n * D + c]);
        cnt++;
    }
    atomicAdd(&g_pool[cur * D + c], acc);
    if (c == 0) atomicAdd(&g_cnt[cur], cnt);
}

// ---------------- head1: per-graph pooled mean + ogt MLP + f1 ----------------
__global__ void head1_kernel(const float* __restrict__ ogt,
                             const float* __restrict__ Wo1, const float* __restrict__ bo1,
                             const float* __restrict__ Wo2, const float* __restrict__ bo2,
                             const float* __restrict__ Wf1, const float* __restrict__ bf1) {
    __shared__ float sf[138];
    __shared__ float o1s[20];
    int g = blockIdx.x;
    int t = threadIdx.x;

    if (t < 128) sf[t] = g_pool[g * D + t] / (float)g_cnt[g];
    if (t < 20) o1s[t] = lrelu(ogt[g] * Wo1[t] + bo1[t]);
    __syncthreads();
    if (t < 10) {
        float s = bo2[t];
#pragma unroll
        for (int k = 0; k < 20; k++) s += o1s[k] * Wo2[k * 10 + t];
        sf[128 + t] = lrelu(s);
    }
    __syncthreads();
    if (t < 92) {
        float s = bf1[t];
        for (int k = 0; k < 138; k++) s += sf[k] * Wf1[k * 92 + t];
        g_f1[g * 92 + t] = lrelu(s);
    }
}

// ---------------- head2: BN1 -> f2 -> BN2 -> out ----------------
#define H2_F1 (N_GRAPHS * 92)
#define H2_F2 (N_GRAPHS * 46)
#define HEAD2_SMEM_BYTES ((H2_F1 + H2_F2 + 92 + 92 + 46 + 46) * 4)
__global__ void head2_kernel(const float* __restrict__ g1, const float* __restrict__ be1,
                             const float* __restrict__ Wf2, const float* __restrict__ bf2,
                             const float* __restrict__ g2, const float* __restrict__ be2,
                             const float* __restrict__ Wf3, const float* __restrict__ bf3,
                             float* __restrict__ out) {
    extern __shared__ float sh[];
    float* f1 = sh;
    float* f2 = f1 + H2_F1;
    float* sc1 = f2 + H2_F2;
    float* ss1 = sc1 + 92;
    float* sc2 = ss1 + 92;
    float* ss2 = sc2 + 46;
    int t = threadIdx.x;
    const int NT = 512;

    for (int i = t; i < H2_F1; i += NT) f1[i] = g_f1[i];
    __syncthreads();

    if (t < 92) {
        float m = 0.f;
        for (int g = 0; g < N_GRAPHS; g++) m += f1[g * 92 + t];
        m *= (1.0f / N_GRAPHS);
        float var = 0.f;
        for (int g = 0; g < N_GRAPHS; g++) {
            float d = f1[g * 92 + t] - m;
            var += d * d;
        }
        var *= (1.0f / N_GRAPHS);
        float rs = rsqrtf(var + BN_EPS);
        sc1[t] = g1[t] * rs;
        ss1[t] = be1[t] - m * g1[t] * rs;
    }
    __syncthreads();

    for (int idx = t; idx < N_GRAPHS * 46; idx += NT) {
        int g = idx / 46, j = idx % 46;
        float s = bf2[j];
        for (int k = 0; k < 92; k++)
            s += (f1[g * 92 + k] * sc1[k] + ss1[k]) * Wf2[k * 46 + j];
        f2[g * 46 + j] = lrelu(s);
    }
    __syncthreads();

    if (t < 46) {
        float m = 0.f;
        for (int g = 0; g < N_GRAPHS; g++) m += f2[g * 46 + t];
        m *= (1.0f / N_GRAPHS);
        float var = 0.f;
        for (int g = 0; g < N_GRAPHS; g++) {
            float d = f2[g * 46 + t] - m;
            var += d * d;
        }
        var *= (1.0f / N_GRAPHS);
        float rs = rsqrtf(var + BN_EPS);
        sc2[t] = g2[t] * rs;
        ss2[t] = be2[t] - m * g2[t] * rs;
    }
    __syncthreads();

    if (t < N_GRAPHS) {
        float s = bf3[0];
#pragma unroll
        for (int k = 0; k < 46; k++)
            s += (f2[t * 46 + k] * sc2[k] + ss2[k]) * Wf3[k];
        out[t] = s;
    }
}

// ---------------- launch ----------------
extern "C" void kernel_launch(void* const* d_in, const int* in_sizes, int n_in,
                              void* d_out, int out_size) {
    const float* x    = (const float*)d_in[0];
    const int*   ei   = (const int*)d_in[1];
    const int*   batch= (const int*)d_in[2];
    const float* ogt  = (const float*)d_in[3];
    const float* W1   = (const float*)d_in[4];
    const float* b1   = (const float*)d_in[5];
    const float* W2   = (const float*)d_in[6];
    const float* b2   = (const float*)d_in[7];
    const float* W3   = (const float*)d_in[8];
    const float* b3   = (const float*)d_in[9];
    const float* Wo1  = (const float*)d_in[10];
    const float* bo1  = (const float*)d_in[11];
    const float* Wo2  = (const float*)d_in[12];
    const float* bo2  = (const float*)d_in[13];
    const float* Wf1  = (const float*)d_in[14];
    const float* bf1  = (const float*)d_in[15];
    const float* g1   = (const float*)d_in[16];
    const float* be1  = (const float*)d_in[17];
    const float* Wf2  = (const float*)d_in[18];
    const float* bf2  = (const float*)d_in[19];
    const float* g2   = (const float*)d_in[20];
    const float* be2  = (const float*)d_in[21];
    const float* Wf3  = (const float*)d_in[22];
    const float* bf3  = (const float*)d_in[23];
    float* out = (float*)d_out;

    const int* src = ei;
    const int* dst = ei + N_EDGES;

    __half *hw, *h1, *h2, *wsw;
    cudaGetSymbolAddress((void**)&hw, g_hw);
    cudaGetSymbolAddress((void**)&h1, g_h1);
    cudaGetSymbolAddress((void**)&h2, g_h2);
    cudaGetSymbolAddress((void**)&wsw, g_Wsw);

    cudaFuncSetAttribute(mma_gemm_kernel<float>, cudaFuncAttributeMaxDynamicSharedMemorySize, GEMM_SMEM);
    cudaFuncSetAttribute(mma_gemm_kernel<__half>, cudaFuncAttributeMaxDynamicSharedMemorySize, GEMM_SMEM);
    cudaFuncSetAttribute(head2_kernel, cudaFuncAttributeMaxDynamicSharedMemorySize, HEAD2_SMEM_BYTES);

    // one-time host-side stream/event objects (no device memory involved)
    static cudaStream_t s2 = 0;
    static cudaEvent_t evA = 0, evB = 0;
    if (s2 == 0) {
        cudaStreamCreateWithFlags(&s2, cudaStreamNonBlocking);
        cudaEventCreateWithFlags(&evA, cudaEventDisableTiming);
        cudaEventCreateWithFlags(&evB, cudaEventDisableTiming);
    }

    const int GEMM_GRID = (N_NODES + GEMM_ROWS - 1) / GEMM_ROWS;   // 391
    const int AGG_GRID = N_NODES / 16;   // 512 threads = 16 warps/block
    const int EDGE_PAIR_GRID = (N_EDGES / 2 + 255) / 256;          // 1563

    // stream 0: prep -> (fork) -> CSR chain; s2: gemm1 in parallel
    prep_kernel<<<ZERO_BLOCKS + 3, 256>>>(W1, W2, W3);
    cudaEventRecord(evA, 0);

    degree_kernel<<<EDGE_PAIR_GRID, 256>>>(dst);
    scan_sums_kernel<<<SCAN_G, SCAN_B>>>();

    cudaStreamWaitEvent(s2, evA, 0);
    mma_gemm_kernel<float><<<GEMM_GRID, 512, GEMM_SMEM, s2>>>(x, wsw, hw, N_NODES);
    cudaEventRecord(evB, s2);

    scan_apply_kernel<<<SCAN_G, SCAN_B>>>();
    fill_kernel<<<EDGE_PAIR_GRID, 256>>>(src, dst);

    cudaStreamWaitEvent(0, evB, 0);   // join gemm1 before agg1

    agg_kernel<<<AGG_GRID, 512>>>(hw, b1, h1);

    mma_gemm_kernel<__half><<<GEMM_GRID, 512, GEMM_SMEM>>>(h1, wsw + D * D, hw, N_NODES);
    agg_kernel<<<AGG_GRID, 512>>>(hw, b2, h2);

    mma_gemm_kernel<__half><<<GEMM_GRID, 512, GEMM_SMEM>>>(h2, wsw + 2 * D * D, hw, N_NODES);
    agg_kernel<<<AGG_GRID, 512>>>(hw, b3, h1);

    pool_kernel<<<N_NODES / POOL_NODES, 128>>>(h1, batch);

    head1_kernel<<<N_GRAPHS, 128>>>(ogt, Wo1, bo1, Wo2, bo2, Wf1, bf1);
    head2_kernel<<<1, 512, HEAD2_SMEM_BYTES>>>(g1, be1, Wf2, bf2, g2, be2, Wf3, bf3, out);
}

// round 17
// speedup vs baseline: 1.1481x; 1.0085x over previous
#include <cuda_runtime.h>
#include <cuda_fp16.h>
#include <math.h>
#include <cstdint>

#define N_NODES 50000
#define N_EDGES 800000
#define N_GRAPHS 100
#define D 128
#define NEG 0.01f
#define BN_EPS 1e-5f

// ---------------- scratch (device globals: allocation-free) ----------------
__device__ __half g_hw[N_NODES * D];   // messages h@W in fp16
__device__ __half g_h1[N_NODES * D];   // layer outputs in fp16 (ping)
__device__ __half g_h2[N_NODES * D];   // (pong)
__device__ int   g_degcnt[N_NODES];
__device__ float g_dinv[N_NODES];
__device__ int   g_rowptr[N_NODES + 1];
__device__ int   g_fill[N_NODES];
__device__ uint2 g_edge[N_EDGES];      // (src, enorm) packed
__device__ float g_pool[N_GRAPHS * D];
__device__ int   g_cnt[N_GRAPHS];
__device__ float g_f1[N_GRAPHS * 92];
// W^T in fp16, PRE-SWIZZLED into the ldmatrix tile layout, per layer (32KB each)
__device__ __half g_Wsw[3 * D * D];
#define SCAN_B 512
#define SCAN_G ((N_NODES + SCAN_B - 1) / SCAN_B)   // 98
__device__ int g_bsum[SCAN_G];

__device__ __forceinline__ float lrelu(float v) { return v > 0.f ? v : NEG * v; }

__device__ __forceinline__ uint32_t smem_to_u32(const void* p) {
    uint32_t a;
    asm("{ .reg .u64 t; cvta.to.shared.u64 t, %1; cvt.u32.u64 %0, t; }" : "=r"(a) : "l"(p));
    return a;
}

// tile layout: rows x 128 cols fp16, 256B/row, XOR-16B swizzle
__device__ __forceinline__ uint32_t swz(int row, int col) {
    return (uint32_t)(row * 256 + ((col * 2) ^ ((row & 7) << 4)));
}

// ---------------- prep: zero + W^T fp16 pre-swizzle ----------------
#define ZERO_BLOCKS 196
__global__ void prep_kernel(const float* __restrict__ W1, const float* __restrict__ W2,
                            const float* __restrict__ W3) {
    int b = blockIdx.x;
    if (b < ZERO_BLOCKS) {
        int i = b * 256 + threadIdx.x;
        if (i < N_NODES) g_degcnt[i] = 0;
        if (i < N_GRAPHS * D) g_pool[i] = 0.f;
        if (i < N_GRAPHS) g_cnt[i] = 0;
    } else {
        int layer = b - ZERO_BLOCKS;
        const float* W = layer == 0 ? W1 : (layer == 1 ? W2 : W3);
        char* dstb = (char*)(g_Wsw + layer * D * D);
        for (int i = threadIdx.x; i < D * D; i += 256) {
            int n = i >> 7, k = i & 127;             // tile row = n, tile col = k
            __half v = __float2half(W[k * D + n]);
            *(__half*)(dstb + swz(n, k)) = v;
        }
    }
}

// ---------------- degree over dst (2 edges/thread, int2) ----------------
__global__ void degree_kernel(const int* __restrict__ dst) {
    int p = blockIdx.x * blockDim.x + threadIdx.x;     // pair index
    if (p < N_EDGES / 2) {
        int2 d = ((const int2*)dst)[p];
        atomicAdd(&g_degcnt[d.x], 1);
        atomicAdd(&g_degcnt[d.y], 1);
    }
}

// ---------------- scan phase 1: block sums ----------------
__global__ void scan_sums_kernel() {
    __shared__ int wsum[SCAN_B / 32];
    int i = blockIdx.x * SCAN_B + threadIdx.x;
    int v = (i < N_NODES) ? g_degcnt[i] : 0;
    int lane = threadIdx.x & 31, wid = threadIdx.x >> 5;
#pragma unroll
    for (int o = 16; o > 0; o >>= 1) v += __shfl_down_sync(0xFFFFFFFFu, v, o);
    if (lane == 0) wsum[wid] = v;
    __syncthreads();
    if (threadIdx.x == 0) {
        int s = 0;
#pragma unroll
        for (int w = 0; w < SCAN_B / 32; w++) s += wsum[w];
        g_bsum[blockIdx.x] = s;
    }
}

// ---------------- scan phase 2: apply ----------------
__global__ void scan_apply_kernel() {
    __shared__ int wsum[SCAN_B / 32];
    __shared__ int blkoff;
    int t = threadIdx.x;
    if (t < 32) {
        int s = 0;
        for (int j = t; j < (int)blockIdx.x; j += 32) s += g_bsum[j];
#pragma unroll
        for (int o = 16; o > 0; o >>= 1) s += __shfl_down_sync(0xFFFFFFFFu, s, o);
        if (t == 0) blkoff = s;
    }
    int i = blockIdx.x * SCAN_B + t;
    int v = (i < N_NODES) ? g_degcnt[i] : 0;
    int lane = t & 31, wid = t >> 5;
    int val = v;
#pragma unroll
    for (int o = 1; o < 32; o <<= 1) {
        int u = __shfl_up_sync(0xFFFFFFFFu, val, o);
        if (lane >= o) val += u;
    }
    if (lane == 31) wsum[wid] = val;
    __syncthreads();
    if (t == 0) {
        int run = 0;
#pragma unroll
        for (int w = 0; w < SCAN_B / 32; w++) { int x = wsum[w]; wsum[w] = run; run += x; }
    }
    __syncthreads();
    int incl = val + wsum[wid] + blkoff;
    if (i < N_NODES) {
        g_rowptr[i + 1] = incl;
        g_fill[i] = incl - v;
        g_dinv[i] = rsqrtf((float)v + 1.0f);
    }
    if (i == 0) g_rowptr[0] = 0;
}

// ---------------- bucket edges by dst (2 edges/thread, int2) ----------------
__global__ void fill_kernel(const int* __restrict__ src, const int* __restrict__ dst) {
    int p = blockIdx.x * blockDim.x + threadIdx.x;     // pair index
    if (p < N_EDGES / 2) {
        int2 s = ((const int2*)src)[p];
        int2 d = ((const int2*)dst)[p];
        int pos0 = atomicAdd(&g_fill[d.x], 1);
        int pos1 = atomicAdd(&g_fill[d.y], 1);
        g_edge[pos0] = make_uint2((uint32_t)s.x, __float_as_uint(g_dinv[s.x] * g_dinv[d.x]));
        g_edge[pos1] = make_uint2((uint32_t)s.y, __float_as_uint(g_dinv[s.y] * g_dinv[d.y]));
    }
}

// ============== HMMA GEMM: hw[N,128] = A[N,128] @ W, fp16, 128-row tiles ==============
// 512 threads / 16 warps; warp owns 16 rows x 64 cols -> acc[8][4] = 32 regs.
// smem: A 32KB + B 32KB = 64KB -> 2 CTAs/SM. One tile per CTA, B staged first
// (measured-best R12 configuration).
#define SM_A 0
#define SM_B 32768
#define GEMM_SMEM 65536
#define GEMM_ROWS 128

__device__ __forceinline__ void ldsm_x4(uint32_t a[4], uint32_t addr) {
    asm volatile("ldmatrix.sync.aligned.m8n8.x4.shared.b16 {%0,%1,%2,%3}, [%4];"
        : "=r"(a[0]), "=r"(a[1]), "=r"(a[2]), "=r"(a[3]) : "r"(addr));
}

__device__ __forceinline__ void mma_f16(float c[4], const uint32_t a[4], uint32_t b0, uint32_t b1) {
    asm volatile("mma.sync.aligned.m16n8k16.row.col.f32.f16.f16.f32 "
        "{%0,%1,%2,%3}, {%4,%5,%6,%7}, {%8,%9}, {%0,%1,%2,%3};"
        : "+f"(c[0]), "+f"(c[1]), "+f"(c[2]), "+f"(c[3])
        : "r"(a[0]), "r"(a[1]), "r"(a[2]), "r"(a[3]), "r"(b0), "r"(b1));
}

// stage one 128-row A tile into swizzled smem (fp32 or fp16 source)
__device__ __forceinline__ void stage_a_f32(char* smem, const float* A, int rb, int nrows, int tid) {
#pragma unroll
    for (int it = 0; it < 16; it++) {
        int i = tid + it * 512;
        int row = i >> 6, cp = i & 63;
        float2 v = make_float2(0.f, 0.f);
        if (rb + row < nrows) v = ((const float2*)A)[(size_t)(rb + row) * 64 + cp];
        *(__half2*)(smem + SM_A + swz(row, cp * 2)) = __floats2half2_rn(v.x, v.y);
    }
}
__device__ __forceinline__ void stage_a_f16(char* smem, const __half* A, int rb, int nrows, int tid) {
#pragma unroll
    for (int it = 0; it < 4; it++) {
        int i = tid + it * 512;                 // 0..2047
        int row = i >> 4, ch = i & 15;          // ch = 16B chunk (8 halves)
        uint4 v = make_uint4(0, 0, 0, 0);
        if (rb + row < nrows) v = ((const uint4*)A)[(size_t)(rb + row) * 16 + ch];
        *(uint4*)(smem + SM_A + swz(row, ch * 8)) = v;
    }
}

template <typename T>
__global__ __launch_bounds__(512, 2)
void mma_gemm_kernel(const T* __restrict__ A,
                     const __half* __restrict__ Wsw,   // pre-swizzled 32KB tile
                     __half* __restrict__ C, int nrows) {
    extern __shared__ char smem[];
    uint32_t sb = smem_to_u32(smem);
    int tid = threadIdx.x;
    int wid = tid >> 5, lane = tid & 31;
    int rb = blockIdx.x * GEMM_ROWS;

    // stage B (32KB)
    {
        const uint4* s = (const uint4*)Wsw;
        uint4* d = (uint4*)(smem + SM_B);
#pragma unroll
        for (int it = 0; it < 4; it++) d[tid + it * 512] = s[tid + it * 512];
    }
    // stage A
    if (sizeof(T) == 4) stage_a_f32(smem, (const float*)A, rb, nrows, tid);
    else                stage_a_f16(smem, (const __half*)A, rb, nrows, tid);
    __syncthreads();

    float acc[8][4];
#pragma unroll
    for (int n = 0; n < 8; n++)
#pragma unroll
        for (int j = 0; j < 4; j++) acc[n][j] = 0.f;

    int rowband = wid >> 1;          // 0..7 -> rows rowband*16..+15
    int colhalf = wid & 1;           // 0..1 -> cols colhalf*64..+63
    int mat = lane >> 3, r8 = lane & 7;
    int arow = rowband * 16 + r8 + (mat & 1) * 8;
    int acoloff = (mat >> 1) * 8;
    int bnbase = (mat >> 1) * 8 + r8;
    int bkoff = (mat & 1) * 8;
    uint32_t bBase = sb + SM_B + (uint32_t)(colhalf * 64 * 256);
    uint32_t aBase = sb + SM_A;

#pragma unroll
    for (int k8 = 0; k8 < 8; k8++) {
        int k0 = k8 * 16;
        uint32_t a[4];
        ldsm_x4(a, aBase + swz(arow, k0 + acoloff));
#pragma unroll
        for (int ntp = 0; ntp < 4; ntp++) {
            uint32_t b[4];
            ldsm_x4(b, bBase + (uint32_t)(ntp * 4096) + swz(bnbase, k0 + bkoff));
            mma_f16(acc[2 * ntp], a, b[0], b[1]);
            mma_f16(acc[2 * ntp + 1], a, b[2], b[3]);
        }
    }

    // epilogue: fp32 fragments -> fp16 C
    int mrow = rb + rowband * 16 + (lane >> 2);
    int nc0 = colhalf * 64 + (lane & 3) * 2;
    bool ok0 = mrow < nrows, ok1 = (mrow + 8) < nrows;
#pragma unroll
    for (int nt = 0; nt < 8; nt++) {
        if (ok0) *(__half2*)(C + (size_t)mrow * 128 + nt * 8 + nc0) =
            __floats2half2_rn(acc[nt][0], acc[nt][1]);
        if (ok1) *(__half2*)(C + (size_t)(mrow + 8) * 128 + nt * 8 + nc0) =
            __floats2half2_rn(acc[nt][2], acc[nt][3]);
    }
}

// ---------------- aggregation: fp16 gather, fp32 accum, masked-chunk tail ----------------
// ONLY change vs measured-best: __launch_bounds__(512, 3) -> caps regs at ~42,
// 3 CTAs/SM = 48 resident warps (+50% outstanding gathers).
__global__ __launch_bounds__(512, 3)
void agg_kernel(const __half* __restrict__ hw, const float* __restrict__ bias,
                __half* __restrict__ out) {
    int warp = (blockIdx.x * blockDim.x + threadIdx.x) >> 5;
    if (warp >= N_NODES) return;
    int lane = threadIdx.x & 31;

    int beg = g_rowptr[warp];
    int end = g_rowptr[warp + 1];
    float dv = g_dinv[warp];
    float sn = dv * dv;

    const uint2* hv = (const uint2*)hw;   // lane covers cols lane*4..+3
    float4 acc;
    {
        uint2 r = hv[(size_t)warp * 32 + lane];
        float2 f0 = __half22float2(*(__half2*)&r.x);
        float2 f1 = __half22float2(*(__half2*)&r.y);
        acc = make_float4(f0.x * sn, f0.y * sn, f1.x * sn, f1.y * sn);
    }

    int e = beg;
    for (; e + 8 <= end; e += 8) {
        uint2 ed[8];
        uint2 r[8];
#pragma unroll
        for (int j = 0; j < 8; j++) ed[j] = g_edge[e + j];
#pragma unroll
        for (int j = 0; j < 8; j++) r[j] = hv[(size_t)ed[j].x * 32 + lane];
#pragma unroll
        for (int j = 0; j < 8; j++) {
            float w = __uint_as_float(ed[j].y);
            float2 a0 = __half22float2(*(__half2*)&r[j].x);
            float2 b0 = __half22float2(*(__half2*)&r[j].y);
            acc.x += w * a0.x;
            acc.y += w * a0.y;
            acc.z += w * b0.x;
            acc.w += w * b0.y;
        }
    }
    if (e < end) {
        // masked chunk of 8: dummy edges use own row (L1-resident) with weight 0
        uint2 ed[8];
        uint2 r[8];
        uint32_t srcs[8];
        float ws[8];
#pragma unroll
        for (int j = 0; j < 8; j++) {
            bool ok = (e + j) < end;
            int idx = ok ? (e + j) : (end - 1);
            ed[j] = g_edge[idx];
            srcs[j] = ok ? ed[j].x : (uint32_t)warp;
            ws[j] = ok ? __uint_as_float(ed[j].y) : 0.f;
        }
#pragma unroll
        for (int j = 0; j < 8; j++) r[j] = hv[(size_t)srcs[j] * 32 + lane];
#pragma unroll
        for (int j = 0; j < 8; j++) {
            float2 a0 = __half22float2(*(__half2*)&r[j].x);
            float2 b0 = __half22float2(*(__half2*)&r[j].y);
            acc.x += ws[j] * a0.x;
            acc.y += ws[j] * a0.y;
            acc.z += ws[j] * b0.x;
            acc.w += ws[j] * b0.y;
        }
    }
    float4 b = *(const float4*)(bias + lane * 4);
    __half2 o0 = __floats2half2_rn(lrelu(acc.x + b.x), lrelu(acc.y + b.y));
    __half2 o1 = __floats2half2_rn(lrelu(acc.z + b.z), lrelu(acc.w + b.w));
    uint2 pk;
    pk.x = *(uint32_t*)&o0;
    pk.y = *(uint32_t*)&o1;
    *((uint2*)(out + (size_t)warp * 128 + lane * 4)) = pk;
}

// ---------------- per-graph sum pool + counts (fp16 input) ----------------
#define POOL_NODES 50
__global__ void pool_kernel(const __half* __restrict__ h, const int* __restrict__ batch) {
    int c = threadIdx.x;
    int base = blockIdx.x * POOL_NODES;
    int cur = batch[base];
    float acc = 0.f;
    int cnt = 0;
    for (int i = 0; i < POOL_NODES; i++) {
        int n = base + i;
        int g = batch[n];
        if (g != cur) {
            atomicAdd(&g_pool[cur * D + c], acc);
            if (c == 0) atomicAdd(&g_cnt[cur], cnt);
            acc = 0.f; cnt = 0;
            cur = g;
        }
        acc += __half2float(h[(size_t)n * D + c]);
        cnt++;
    }
    atomicAdd(&g_pool[cur * D + c], acc);
    if (c == 0) atomicAdd(&g_cnt[cur], cnt);
}

// ---------------- head1: per-graph pooled mean + ogt MLP + f1 ----------------
__global__ void head1_kernel(const float* __restrict__ ogt,
                             const float* __restrict__ Wo1, const float* __restrict__ bo1,
                             const float* __restrict__ Wo2, const float* __restrict__ bo2,
                             const float* __restrict__ Wf1, const float* __restrict__ bf1) {
    __shared__ float sf[138];
    __shared__ float o1s[20];
    int g = blockIdx.x;
    int t = threadIdx.x;

    if (t < 128) sf[t] = g_pool[g * D + t] / (float)g_cnt[g];
    if (t < 20) o1s[t] = lrelu(ogt[g] * Wo1[t] + bo1[t]);
    __syncthreads();
    if (t < 10) {
        float s = bo2[t];
#pragma unroll
        for (int k = 0; k < 20; k++) s += o1s[k] * Wo2[k * 10 + t];
        sf[128 + t] = lrelu(s);
    }
    __syncthreads();
    if (t < 92) {
        float s = bf1[t];
        for (int k = 0; k < 138; k++) s += sf[k] * Wf1[k * 92 + t];
        g_f1[g * 92 + t] = lrelu(s);
    }
}

// ---------------- head2: BN1 -> f2 -> BN2 -> out ----------------
#define H2_F1 (N_GRAPHS * 92)
#define H2_F2 (N_GRAPHS * 46)
#define HEAD2_SMEM_BYTES ((H2_F1 + H2_F2 + 92 + 92 + 46 + 46) * 4)
__global__ void head2_kernel(const float* __restrict__ g1, const float* __restrict__ be1,
                             const float* __restrict__ Wf2, const float* __restrict__ bf2,
                             const float* __restrict__ g2, const float* __restrict__ be2,
                             const float* __restrict__ Wf3, const float* __restrict__ bf3,
                             float* __restrict__ out) {
    extern __shared__ float sh[];
    float* f1 = sh;
    float* f2 = f1 + H2_F1;
    float* sc1 = f2 + H2_F2;
    float* ss1 = sc1 + 92;
    float* sc2 = ss1 + 92;
    float* ss2 = sc2 + 46;
    int t = threadIdx.x;
    const int NT = 512;

    for (int i = t; i < H2_F1; i += NT) f1[i] = g_f1[i];
    __syncthreads();

    if (t < 92) {
        float m = 0.f;
        for (int g = 0; g < N_GRAPHS; g++) m += f1[g * 92 + t];
        m *= (1.0f / N_GRAPHS);
        float var = 0.f;
        for (int g = 0; g < N_GRAPHS; g++) {
            float d = f1[g * 92 + t] - m;
            var += d * d;
        }
        var *= (1.0f / N_GRAPHS);
        float rs = rsqrtf(var + BN_EPS);
        sc1[t] = g1[t] * rs;
        ss1[t] = be1[t] - m * g1[t] * rs;
    }
    __syncthreads();

    for (int idx = t; idx < N_GRAPHS * 46; idx += NT) {
        int g = idx / 46, j = idx % 46;
        float s = bf2[j];
        for (int k = 0; k < 92; k++)
            s += (f1[g * 92 + k] * sc1[k] + ss1[k]) * Wf2[k * 46 + j];
        f2[g * 46 + j] = lrelu(s);
    }
    __syncthreads();

    if (t < 46) {
        float m = 0.f;
        for (int g = 0; g < N_GRAPHS; g++) m += f2[g * 46 + t];
        m *= (1.0f / N_GRAPHS);
        float var = 0.f;
        for (int g = 0; g < N_GRAPHS; g++) {
            float d = f2[g * 46 + t] - m;
            var += d * d;
        }
        var *= (1.0f / N_GRAPHS);
        float rs = rsqrtf(var + BN_EPS);
        sc2[t] = g2[t] * rs;
        ss2[t] = be2[t] - m * g2[t] * rs;
    }
    __syncthreads();

    if (t < N_GRAPHS) {
        float s = bf3[0];
#pragma unroll
        for (int k = 0; k < 46; k++)
            s += (f2[t * 46 + k] * sc2[k] + ss2[k]) * Wf3[k];
        out[t] = s;
    }
}

// ---------------- launch ----------------
extern "C" void kernel_launch(void* const* d_in, const int* in_sizes, int n_in,
                              void* d_out, int out_size) {
    const float* x    = (const float*)d_in[0];
    const int*   ei   = (const int*)d_in[1];
    const int*   batch= (const int*)d_in[2];
    const float* ogt  = (const float*)d_in[3];
    const float* W1   = (const float*)d_in[4];
    const float* b1   = (const float*)d_in[5];
    const float* W2   = (const float*)d_in[6];
    const float* b2   = (const float*)d_in[7];
    const float* W3   = (const float*)d_in[8];
    const float* b3   = (const float*)d_in[9];
    const float* Wo1  = (const float*)d_in[10];
    const float* bo1  = (const float*)d_in[11];
    const float* Wo2  = (const float*)d_in[12];
    const float* bo2  = (const float*)d_in[13];
    const float* Wf1  = (const float*)d_in[14];
    const float* bf1  = (const float*)d_in[15];
    const float* g1   = (const float*)d_in[16];
    const float* be1  = (const float*)d_in[17];
    const float* Wf2  = (const float*)d_in[18];
    const float* bf2  = (const float*)d_in[19];
    const float* g2   = (const float*)d_in[20];
    const float* be2  = (const float*)d_in[21];
    const float* Wf3  = (const float*)d_in[22];
    const float* bf3  = (const float*)d_in[23];
    float* out = (float*)d_out;

    const int* src = ei;
    const int* dst = ei + N_EDGES;

    __half *hw, *h1, *h2, *wsw;
    cudaGetSymbolAddress((void**)&hw, g_hw);
    cudaGetSymbolAddress((void**)&h1, g_h1);
    cudaGetSymbolAddress((void**)&h2, g_h2);
    cudaGetSymbolAddress((void**)&wsw, g_Wsw);

    cudaFuncSetAttribute(mma_gemm_kernel<float>, cudaFuncAttributeMaxDynamicSharedMemorySize, GEMM_SMEM);
    cudaFuncSetAttribute(mma_gemm_kernel<__half>, cudaFuncAttributeMaxDynamicSharedMemorySize, GEMM_SMEM);
    cudaFuncSetAttribute(head2_kernel, cudaFuncAttributeMaxDynamicSharedMemorySize, HEAD2_SMEM_BYTES);

    // one-time host-side stream/event objects (no device memory involved)
    static cudaStream_t s2 = 0;
    static cudaEvent_t evA = 0, evB = 0;
    if (s2 == 0) {
        cudaStreamCreateWithFlags(&s2, cudaStreamNonBlocking);
        cudaEventCreateWithFlags(&evA, cudaEventDisableTiming);
        cudaEventCreateWithFlags(&evB, cudaEventDisableTiming);
    }

    const int GEMM_GRID = (N_NODES + GEMM_ROWS - 1) / GEMM_ROWS;   // 391
    const int AGG_GRID = N_NODES / 16;   // 512 threads = 16 warps/block
    const int EDGE_PAIR_GRID = (N_EDGES / 2 + 255) / 256;          // 1563

    // stream 0: prep -> (fork) -> CSR chain; s2: gemm1 in parallel
    prep_kernel<<<ZERO_BLOCKS + 3, 256>>>(W1, W2, W3);
    cudaEventRecord(evA, 0);

    degree_kernel<<<EDGE_PAIR_GRID, 256>>>(dst);
    scan_sums_kernel<<<SCAN_G, SCAN_B>>>();

    cudaStreamWaitEvent(s2, evA, 0);
    mma_gemm_kernel<float><<<GEMM_GRID, 512, GEMM_SMEM, s2>>>(x, wsw, hw, N_NODES);
    cudaEventRecord(evB, s2);

    scan_apply_kernel<<<SCAN_G, SCAN_B>>>();
    fill_kernel<<<EDGE_PAIR_GRID, 256>>>(src, dst);

    cudaStreamWaitEvent(0, evB, 0);   // join gemm1 before agg1

    agg_kernel<<<AGG_GRID, 512>>>(hw, b1, h1);

    mma_gemm_kernel<__half><<<GEMM_GRID, 512, GEMM_SMEM>>>(h1, wsw + D * D, hw, N_NODES);
    agg_kernel<<<AGG_GRID, 512>>>(hw, b2, h2);

    mma_gemm_kernel<__half><<<GEMM_GRID, 512, GEMM_SMEM>>>(h2, wsw + 2 * D * D, hw, N_NODES);
    agg_kernel<<<AGG_GRID, 512>>>(hw, b3, h1);

    pool_kernel<<<N_NODES / POOL_NODES, 128>>>(h1, batch);

    head1_kernel<<<N_GRAPHS, 128>>>(ogt, Wo1, bo1, Wo2, bo2, Wf1, bf1);
    head2_kernel<<<1, 512, HEAD2_SMEM_BYTES>>>(g1, be1, Wf2, bf2, g2, be2, Wf3, bf3, out);
}